// round 1
// baseline (speedup 1.0000x reference)
#include <cuda_runtime.h>
#include <cuda_bf16.h>
#include <math.h>

// ---------------------------------------------------------------------------
// Problem constants
// ---------------------------------------------------------------------------
#define BATCH    8
#define NPTS     4096
#define WIDTH    768
#define HEADS    12
#define LAYERS   8
#define N_LAT    256
#define D_HEAD   64
#define IN_DIM   54
#define BN_ROWS  (BATCH * NPTS)        // 32768
#define LAT_ROWS (BATCH * N_LAT)       // 2048

#define FLAG_RES  1
#define FLAG_GELU 2

// ---------------------------------------------------------------------------
// Scratch (device globals; no allocation allowed)
// ---------------------------------------------------------------------------
__device__ float g_data[BN_ROWS * WIDTH];          // embedded+projected points
__device__ float g_kv  [BN_ROWS * 2 * WIDTH];      // [k | v] per point
__device__ float g_q   [N_LAT * WIDTH];            // cross-attn queries (batch-invariant)
__device__ float g_attn[LAT_ROWS * WIDTH];         // attention output
__device__ float g_x   [LAT_ROWS * WIDTH];         // residual stream
__device__ float g_h   [LAT_ROWS * WIDTH];         // LN output
__device__ float g_qkv [LAT_ROWS * 3 * WIDTH];     // per-layer qkv
__device__ float g_ffn [LAT_ROWS * 4 * WIDTH];     // MLP hidden

// ---------------------------------------------------------------------------
// Fourier embed + input projection: data = embed(pc,feats) @ in_W.T + in_b
// one block per row (B*N rows), 256 threads
// ---------------------------------------------------------------------------
__global__ void embed_kernel(const float* __restrict__ pc,
                             const float* __restrict__ feats,
                             const float* __restrict__ inW,
                             const float* __restrict__ inb,
                             float* __restrict__ out)
{
    __shared__ float e[IN_DIM];
    const int row = blockIdx.x;
    const int t = threadIdx.x;
    if (t < IN_DIM) {
        float v;
        if (t < 3) {
            v = pc[row * 3 + t];
        } else if (t < 27) {
            int j = (t - 3) >> 3, f = (t - 3) & 7;
            v = sinf(pc[row * 3 + j] * (float)(1 << f));
        } else if (t < 51) {
            int j = (t - 27) >> 3, f = (t - 27) & 7;
            v = cosf(pc[row * 3 + j] * (float)(1 << f));
        } else {
            v = feats[row * 3 + (t - 51)];
        }
        e[t] = v;
    }
    __syncthreads();
    #pragma unroll
    for (int rep = 0; rep < 3; ++rep) {
        int o = t + rep * 256;
        const float* w = inW + o * IN_DIM;
        float s = inb[o];
        #pragma unroll
        for (int k = 0; k < IN_DIM; ++k) s = fmaf(w[k], e[k], s);
        out[(long)row * WIDTH + o] = s;
    }
}

// ---------------------------------------------------------------------------
// SGEMM: C[M,N] = A[M,K] @ B[N,K]^T + bias (+res) (gelu)
// 128x128x8 tile, 256 threads, 8x8 per thread, double-buffered smem
// Requires: M%128==0, N%128==0, K%8==0, all pointers 16B aligned.
// ---------------------------------------------------------------------------
__global__ __launch_bounds__(256, 2)
void sgemm_nt(const float* __restrict__ A, const float* __restrict__ Bw,
              const float* __restrict__ bias, const float* __restrict__ Res,
              float* __restrict__ C, int M, int N, int K, int flags)
{
    __shared__ float As[2][8][132];
    __shared__ float Bs[2][8][132];

    const int tid = threadIdx.x;
    const int tx = tid & 15;
    const int ty = tid >> 4;
    const int cm = blockIdx.y * 128;
    const int cn = blockIdx.x * 128;

    const int lr = tid >> 1;        // row within tile 0..127
    const int lk = (tid & 1) * 4;   // 0 or 4

    const float* Aptr = A + (long)(cm + lr) * K + lk;
    const float* Bptr = Bw + (long)(cn + lr) * K + lk;

    float4 a4 = *(const float4*)(Aptr);
    float4 b4 = *(const float4*)(Bptr);
    As[0][lk + 0][lr] = a4.x; As[0][lk + 1][lr] = a4.y;
    As[0][lk + 2][lr] = a4.z; As[0][lk + 3][lr] = a4.w;
    Bs[0][lk + 0][lr] = b4.x; Bs[0][lk + 1][lr] = b4.y;
    Bs[0][lk + 2][lr] = b4.z; Bs[0][lk + 3][lr] = b4.w;
    __syncthreads();

    float acc[8][8];
    #pragma unroll
    for (int i = 0; i < 8; ++i)
        #pragma unroll
        for (int j = 0; j < 8; ++j) acc[i][j] = 0.f;

    const int ktiles = K >> 3;
    for (int t = 0; t < ktiles; ++t) {
        const int cur = t & 1;
        const int nxt = cur ^ 1;
        if (t + 1 < ktiles) {
            a4 = *(const float4*)(Aptr + (t + 1) * 8);
            b4 = *(const float4*)(Bptr + (t + 1) * 8);
        }
        #pragma unroll
        for (int kk = 0; kk < 8; ++kk) {
            float af[8], bf[8];
            *(float4*)&af[0] = *(const float4*)&As[cur][kk][ty * 4];
            *(float4*)&af[4] = *(const float4*)&As[cur][kk][64 + ty * 4];
            *(float4*)&bf[0] = *(const float4*)&Bs[cur][kk][tx * 4];
            *(float4*)&bf[4] = *(const float4*)&Bs[cur][kk][64 + tx * 4];
            #pragma unroll
            for (int i = 0; i < 8; ++i)
                #pragma unroll
                for (int j = 0; j < 8; ++j)
                    acc[i][j] = fmaf(af[i], bf[j], acc[i][j]);
        }
        if (t + 1 < ktiles) {
            As[nxt][lk + 0][lr] = a4.x; As[nxt][lk + 1][lr] = a4.y;
            As[nxt][lk + 2][lr] = a4.z; As[nxt][lk + 3][lr] = a4.w;
            Bs[nxt][lk + 0][lr] = b4.x; Bs[nxt][lk + 1][lr] = b4.y;
            Bs[nxt][lk + 2][lr] = b4.z; Bs[nxt][lk + 3][lr] = b4.w;
        }
        __syncthreads();
    }

    // epilogue
    #pragma unroll
    for (int i = 0; i < 8; ++i) {
        const int row = cm + ((i < 4) ? (ty * 4 + i) : (64 + ty * 4 + i - 4));
        const long rbase = (long)row * N;
        #pragma unroll
        for (int g = 0; g < 2; ++g) {
            const int c0 = cn + g * 64 + tx * 4;
            float v[4];
            #pragma unroll
            for (int j = 0; j < 4; ++j) v[j] = acc[i][g * 4 + j] + bias[c0 + j];
            if (flags & FLAG_GELU) {
                #pragma unroll
                for (int j = 0; j < 4; ++j)
                    v[j] = 0.5f * v[j] * (1.0f + erff(v[j] * 0.70710678118654752f));
            }
            if (flags & FLAG_RES) {
                float4 r = *(const float4*)&Res[rbase + c0];
                v[0] += r.x; v[1] += r.y; v[2] += r.z; v[3] += r.w;
            }
            float4 o; o.x = v[0]; o.y = v[1]; o.z = v[2]; o.w = v[3];
            *(float4*)&C[rbase + c0] = o;
        }
    }
}

// ---------------------------------------------------------------------------
// LayerNorm over last dim (768). One block per row.
// ---------------------------------------------------------------------------
__global__ void ln_kernel(const float* __restrict__ X,
                          const float* __restrict__ s,
                          const float* __restrict__ b,
                          float* __restrict__ Y)
{
    const int row = blockIdx.x;
    const int t = threadIdx.x;
    const float* x = X + (long)row * WIDTH;
    float v0 = x[t], v1 = x[t + 256], v2 = x[t + 512];
    float sum = v0 + v1 + v2;
    float sq = v0 * v0 + v1 * v1 + v2 * v2;
    __shared__ float red[16];
    #pragma unroll
    for (int o = 16; o; o >>= 1) {
        sum += __shfl_xor_sync(0xffffffffu, sum, o);
        sq  += __shfl_xor_sync(0xffffffffu, sq,  o);
    }
    const int w = t >> 5, l = t & 31;
    if (l == 0) { red[w] = sum; red[w + 8] = sq; }
    __syncthreads();
    if (t < 32) {
        float a = (l < 8) ? red[l] : 0.f;
        float c = (l < 8) ? red[l + 8] : 0.f;
        #pragma unroll
        for (int o = 4; o; o >>= 1) {
            a += __shfl_xor_sync(0xffffffffu, a, o);
            c += __shfl_xor_sync(0xffffffffu, c, o);
        }
        if (l == 0) { red[0] = a; red[1] = c; }
    }
    __syncthreads();
    const float mu = red[0] * (1.f / WIDTH);
    const float var = red[1] * (1.f / WIDTH) - mu * mu;
    const float rs = rsqrtf(var + 1e-5f);
    float* y = Y + (long)row * WIDTH;
    y[t]       = (v0 - mu) * rs * s[t]       + b[t];
    y[t + 256] = (v1 - mu) * rs * s[t + 256] + b[t + 256];
    y[t + 512] = (v2 - mu) * rs * s[t + 512] + b[t + 512];
}

// ---------------------------------------------------------------------------
// Flash attention (fp32 online softmax), 128 query rows per CTA, 64-key chunks.
// S pass and PV pass both register-blocked 8x4 with P round-tripped via smem.
// grid = (Lq/128, HEADS, BATCH); 256 threads.
// Q/K/V addressed via batch/row/head strides; K and V share kRS/kBS/kHS.
// ---------------------------------------------------------------------------
#define FLASH_SMEM ((2 * 128 * 65 + 2 * 64 * 65) * 4)

__global__ __launch_bounds__(256)
void flash_kernel(const float* __restrict__ Qp, const float* __restrict__ Kp,
                  const float* __restrict__ Vp, float* __restrict__ Op,
                  int Lk, int qRS, int kRS, int oRS,
                  long qBS, long kBS, long oBS,
                  int qHS, int kHS, int oHS)
{
    extern __shared__ float sm[];
    float* Qs = sm;                 // 128 x 65
    float* Ps = sm + 128 * 65;      // 128 x 65
    float* Ks = sm + 2 * 128 * 65;  // 64 x 65
    float* Vs = Ks + 64 * 65;       // 64 x 65

    const int tid = threadIdx.x;
    const int tx = tid & 15;
    const int ty = tid >> 4;
    const int qt = blockIdx.x, h = blockIdx.y, b = blockIdx.z;

    const float* Q  = Qp + (long)b * qBS + h * qHS + (long)(qt * 128) * qRS;
    const float* Kb = Kp + (long)b * kBS + h * kHS;
    const float* Vb = Vp + (long)b * kBS + h * kHS;
    float*       O  = Op + (long)b * oBS + h * oHS + (long)(qt * 128) * oRS;

    for (int idx = tid; idx < 128 * 64; idx += 256) {
        int r = idx >> 6, d = idx & 63;
        Qs[r * 65 + d] = Q[(long)r * qRS + d];
    }

    float m[8], l[8], o[8][4];
    #pragma unroll
    for (int i = 0; i < 8; ++i) {
        m[i] = -3.0e38f; l[i] = 0.f;
        #pragma unroll
        for (int j = 0; j < 4; ++j) o[i][j] = 0.f;
    }
    __syncthreads();

    for (int c0 = 0; c0 < Lk; c0 += 64) {
        for (int idx = tid; idx < 64 * 64; idx += 256) {
            int r = idx >> 6, d = idx & 63;
            Ks[r * 65 + d] = Kb[(long)(c0 + r) * kRS + d];
            Vs[r * 65 + d] = Vb[(long)(c0 + r) * kRS + d];
        }
        __syncthreads();

        // S = (Q K^T) * 1/8
        float s[8][4];
        #pragma unroll
        for (int i = 0; i < 8; ++i)
            #pragma unroll
            for (int j = 0; j < 4; ++j) s[i][j] = 0.f;
        #pragma unroll 16
        for (int d = 0; d < 64; ++d) {
            float a[8], bf[4];
            #pragma unroll
            for (int i = 0; i < 8; ++i) a[i] = Qs[(ty * 8 + i) * 65 + d];
            #pragma unroll
            for (int j = 0; j < 4; ++j) bf[j] = Ks[(tx * 4 + j) * 65 + d];
            #pragma unroll
            for (int i = 0; i < 8; ++i)
                #pragma unroll
                for (int j = 0; j < 4; ++j)
                    s[i][j] = fmaf(a[i], bf[j], s[i][j]);
        }

        // online softmax + stash P in smem
        #pragma unroll
        for (int i = 0; i < 8; ++i) {
            #pragma unroll
            for (int j = 0; j < 4; ++j) s[i][j] *= 0.125f;
            float mx = fmaxf(fmaxf(s[i][0], s[i][1]), fmaxf(s[i][2], s[i][3]));
            #pragma unroll
            for (int off = 1; off < 16; off <<= 1)
                mx = fmaxf(mx, __shfl_xor_sync(0xffffffffu, mx, off));
            const float mnew = fmaxf(m[i], mx);
            const float corr = __expf(m[i] - mnew);
            m[i] = mnew;
            float rsum = 0.f;
            #pragma unroll
            for (int j = 0; j < 4; ++j) {
                s[i][j] = __expf(s[i][j] - mnew);
                rsum += s[i][j];
            }
            #pragma unroll
            for (int off = 1; off < 16; off <<= 1)
                rsum += __shfl_xor_sync(0xffffffffu, rsum, off);
            l[i] = l[i] * corr + rsum;
            #pragma unroll
            for (int j = 0; j < 4; ++j) {
                o[i][j] *= corr;
                Ps[(ty * 8 + i) * 65 + tx * 4 + j] = s[i][j];
            }
        }
        __syncthreads();

        // O += P V
        #pragma unroll 16
        for (int c = 0; c < 64; ++c) {
            float a[8], bf[4];
            #pragma unroll
            for (int i = 0; i < 8; ++i) a[i] = Ps[(ty * 8 + i) * 65 + c];
            #pragma unroll
            for (int j = 0; j < 4; ++j) bf[j] = Vs[c * 65 + tx * 4 + j];
            #pragma unroll
            for (int i = 0; i < 8; ++i)
                #pragma unroll
                for (int j = 0; j < 4; ++j)
                    o[i][j] = fmaf(a[i], bf[j], o[i][j]);
        }
        __syncthreads();
    }

    #pragma unroll
    for (int i = 0; i < 8; ++i) {
        const float inv = 1.f / l[i];
        const int r = ty * 8 + i;
        #pragma unroll
        for (int j = 0; j < 4; ++j)
            O[(long)r * oRS + tx * 4 + j] = o[i][j] * inv;
    }
}

// ---------------------------------------------------------------------------
// Simple copy
// ---------------------------------------------------------------------------
__global__ void copy_kernel(const float* __restrict__ src, float* __restrict__ dst, int n)
{
    int i = blockIdx.x * 256 + threadIdx.x;
    if (i < n) dst[i] = src[i];
}

// ---------------------------------------------------------------------------
// kernel_launch
// ---------------------------------------------------------------------------
extern "C" void kernel_launch(void* const* d_in, const int* in_sizes, int n_in,
                              void* d_out, int out_size)
{
    const float* pc       = (const float*)d_in[0];
    const float* feats    = (const float*)d_in[1];
    const float* query    = (const float*)d_in[2];
    const float* in_W     = (const float*)d_in[3];
    const float* in_b     = (const float*)d_in[4];
    const float* ca_qkv_W = (const float*)d_in[5];
    const float* ca_qkv_b = (const float*)d_in[6];
    const float* ca_proj_W= (const float*)d_in[7];
    const float* ca_proj_b= (const float*)d_in[8];
    const float* ln1_s    = (const float*)d_in[9];
    const float* ln1_b    = (const float*)d_in[10];
    const float* qkv_W    = (const float*)d_in[11];
    const float* qkv_b    = (const float*)d_in[12];
    const float* proj_W   = (const float*)d_in[13];
    const float* proj_b   = (const float*)d_in[14];
    const float* ln2_s    = (const float*)d_in[15];
    const float* ln2_b    = (const float*)d_in[16];
    const float* fc_W     = (const float*)d_in[17];
    const float* fc_b     = (const float*)d_in[18];
    const float* fc2_W    = (const float*)d_in[19];
    const float* fc2_b    = (const float*)d_in[20];

    float *data, *kv, *qb, *attn, *x, *h, *qkvb, *ffn;
    cudaGetSymbolAddress((void**)&data, g_data);
    cudaGetSymbolAddress((void**)&kv,   g_kv);
    cudaGetSymbolAddress((void**)&qb,   g_q);
    cudaGetSymbolAddress((void**)&attn, g_attn);
    cudaGetSymbolAddress((void**)&x,    g_x);
    cudaGetSymbolAddress((void**)&h,    g_h);
    cudaGetSymbolAddress((void**)&qkvb, g_qkv);
    cudaGetSymbolAddress((void**)&ffn,  g_ffn);

    cudaFuncSetAttribute(flash_kernel, cudaFuncAttributeMaxDynamicSharedMemorySize,
                         FLASH_SMEM);

    // 1) fourier embed + input projection
    embed_kernel<<<BN_ROWS, 256>>>(pc, feats, in_W, in_b, data);

    // 2) kv = data @ ca_qkv_W[768:2304].T + b[768:]
    sgemm_nt<<<dim3((2 * WIDTH) / 128, BN_ROWS / 128), 256>>>(
        data, ca_qkv_W + (long)WIDTH * WIDTH, ca_qkv_b + WIDTH, nullptr, kv,
        BN_ROWS, 2 * WIDTH, WIDTH, 0);

    // 3) q = query @ ca_qkv_W[:768].T + b[:768]   (batch-invariant)
    sgemm_nt<<<dim3(WIDTH / 128, N_LAT / 128), 256>>>(
        query, ca_qkv_W, ca_qkv_b, nullptr, qb, N_LAT, WIDTH, WIDTH, 0);

    // 4) cross attention: latents attend to 4096 points
    flash_kernel<<<dim3(N_LAT / 128, HEADS, BATCH), 256, FLASH_SMEM>>>(
        qb, kv, kv + WIDTH, attn,
        NPTS, WIDTH, 2 * WIDTH, WIDTH,
        0L, (long)NPTS * 2 * WIDTH, (long)N_LAT * WIDTH,
        D_HEAD, D_HEAD, D_HEAD);

    // 5) latents = attn @ ca_proj_W.T + b
    sgemm_nt<<<dim3(WIDTH / 128, LAT_ROWS / 128), 256>>>(
        attn, ca_proj_W, ca_proj_b, nullptr, x, LAT_ROWS, WIDTH, WIDTH, 0);

    // 6) transformer blocks
    for (int L = 0; L < LAYERS; ++L) {
        ln_kernel<<<LAT_ROWS, 256>>>(x, ln1_s + L * WIDTH, ln1_b + L * WIDTH, h);

        sgemm_nt<<<dim3((3 * WIDTH) / 128, LAT_ROWS / 128), 256>>>(
            h, qkv_W + (long)L * 3 * WIDTH * WIDTH, qkv_b + (long)L * 3 * WIDTH,
            nullptr, qkvb, LAT_ROWS, 3 * WIDTH, WIDTH, 0);

        // self-attention: qkv layout per token = heads x [q64|k64|v64]
        flash_kernel<<<dim3(N_LAT / 128, HEADS, BATCH), 256, FLASH_SMEM>>>(
            qkvb, qkvb + D_HEAD, qkvb + 2 * D_HEAD, attn,
            N_LAT, 3 * WIDTH, 3 * WIDTH, WIDTH,
            (long)N_LAT * 3 * WIDTH, (long)N_LAT * 3 * WIDTH, (long)N_LAT * WIDTH,
            3 * D_HEAD, 3 * D_HEAD, D_HEAD);

        sgemm_nt<<<dim3(WIDTH / 128, LAT_ROWS / 128), 256>>>(
            attn, proj_W + (long)L * WIDTH * WIDTH, proj_b + (long)L * WIDTH,
            x, x, LAT_ROWS, WIDTH, WIDTH, FLAG_RES);

        ln_kernel<<<LAT_ROWS, 256>>>(x, ln2_s + L * WIDTH, ln2_b + L * WIDTH, h);

        sgemm_nt<<<dim3((4 * WIDTH) / 128, LAT_ROWS / 128), 256>>>(
            h, fc_W + (long)L * 4 * WIDTH * WIDTH, fc_b + (long)L * 4 * WIDTH,
            nullptr, ffn, LAT_ROWS, 4 * WIDTH, WIDTH, FLAG_GELU);

        float* Cout = (L == LAYERS - 1) ? (float*)d_out : x;
        sgemm_nt<<<dim3(WIDTH / 128, LAT_ROWS / 128), 256>>>(
            ffn, fc2_W + (long)L * WIDTH * 4 * WIDTH, fc2_b + (long)L * WIDTH,
            x, Cout, LAT_ROWS, WIDTH, 4 * WIDTH, FLAG_RES);
    }

    // 7) second output: pc passthrough (if the harness output holds both)
    const int lat_elems = LAT_ROWS * WIDTH;
    const int pc_elems = BATCH * NPTS * 3;
    if (out_size >= lat_elems + pc_elems) {
        copy_kernel<<<(pc_elems + 255) / 256, 256>>>(
            pc, (float*)d_out + lat_elems, pc_elems);
    }
}

// round 8
// speedup vs baseline: 1.7968x; 1.7968x over previous
#include <cuda_runtime.h>
#include <cuda_bf16.h>
#include <math.h>
#include <stdint.h>

// ---------------------------------------------------------------------------
// Problem constants
// ---------------------------------------------------------------------------
#define BATCH    8
#define NPTS     4096
#define WIDTH    768
#define HEADS    12
#define LAYERS   8
#define N_LAT    256
#define D_HEAD   64
#define IN_DIM   54
#define BN_ROWS  (BATCH * NPTS)        // 32768
#define LAT_ROWS (BATCH * N_LAT)       // 2048

#define FLAG_RES  1
#define FLAG_GELU 2

// ---------------------------------------------------------------------------
// Scratch (device globals; no allocation allowed)
// ---------------------------------------------------------------------------
__device__ float g_data[BN_ROWS * WIDTH];
__device__ float g_kv  [BN_ROWS * 2 * WIDTH];
__device__ float g_q   [N_LAT * WIDTH];
__device__ float g_attn[LAT_ROWS * WIDTH];
__device__ float g_x   [LAT_ROWS * WIDTH];
__device__ float g_h   [LAT_ROWS * WIDTH];
__device__ float g_ffn [LAT_ROWS * 4 * WIDTH];

// tf32-rounded weights, one big arena
#define W_CAQKV   0L
#define W_CAPROJ  1769472L
#define W_QKV     2359296L
#define W_PROJ    16515072L
#define W_FC      21233664L
#define W_FC2     40108032L
#define W_TOTAL   58982400L
__device__ float g_wtf[W_TOTAL];

// ---------------------------------------------------------------------------
// Helpers (sm_80+ features only — NO tcgen05, this bench targets plain sm_103)
// ---------------------------------------------------------------------------
__device__ __forceinline__ uint32_t smem_u32(const void* p) {
    uint32_t a;
    asm("{ .reg .u64 t; cvta.to.shared.u64 t, %1; cvt.u32.u64 %0, t; }"
        : "=r"(a) : "l"(p));
    return a;
}
__device__ __forceinline__ void cp16(uint32_t dst, const void* src) {
    asm volatile("cp.async.cg.shared.global [%0], [%1], 16;"
                 :: "r"(dst), "l"(src) : "memory");
}
__device__ __forceinline__ float rna_f(float x) {
    uint32_t u;
    asm("cvt.rna.tf32.f32 %0, %1;" : "=r"(u) : "f"(x));
    return __uint_as_float(u);
}
__device__ __forceinline__ void mma1688(float* c, const uint32_t* a,
                                        uint32_t b0, uint32_t b1) {
    asm volatile(
        "mma.sync.aligned.m16n8k8.row.col.f32.tf32.tf32.f32 "
        "{%0,%1,%2,%3},{%4,%5,%6,%7},{%8,%9},{%0,%1,%2,%3};"
        : "+f"(c[0]), "+f"(c[1]), "+f"(c[2]), "+f"(c[3])
        : "r"(a[0]), "r"(a[1]), "r"(a[2]), "r"(a[3]), "r"(b0), "r"(b1));
}

// ---------------------------------------------------------------------------
// rna tf32 rounding of weights
// ---------------------------------------------------------------------------
__global__ void rna_kernel(const float4* __restrict__ src, float4* __restrict__ dst, int n4)
{
    int i = blockIdx.x * 256 + threadIdx.x;
    if (i >= n4) return;
    float4 v = src[i];
    v.x = rna_f(v.x); v.y = rna_f(v.y); v.z = rna_f(v.z); v.w = rna_f(v.w);
    dst[i] = v;
}

// ---------------------------------------------------------------------------
// tf32 mma.sync GEMM: C[M,N] = A[M,K] @ B[N,K]^T + bias (+res)(gelu+rna)
// CTA tile 128x128, BK=32, double-buffered cp.async, 8 warps x (32x64).
// smem layout: [row][k] with stride 36 floats (conflict-free fragment loads).
// Requires M%128==0, N%128==0, K%32==0, 16B-aligned pointers.
// ---------------------------------------------------------------------------
#define STRIDE 36
#define STAGE_BYTES (128 * STRIDE * 4)         // 18432
#define GEMM_SMEM (4 * STAGE_BYTES)            // A0,A1,B0,B1 = 73728

__device__ __forceinline__ void load_stage(uint32_t abase, uint32_t bbase,
                                           const float* __restrict__ A,
                                           const float* __restrict__ B,
                                           int K, int cm, int cn, int kt, int tid)
{
    const float* Ak = A + (long)cm * K + kt * 32;
    const float* Bk = B + (long)cn * K + kt * 32;
    #pragma unroll
    for (int it = 0; it < 4; ++it) {
        int i = tid + it * 256;
        int r = i >> 3, c = i & 7;
        cp16(abase + r * (STRIDE * 4) + c * 16, Ak + (long)r * K + c * 4);
    }
    #pragma unroll
    for (int it = 0; it < 4; ++it) {
        int i = tid + it * 256;
        int r = i >> 3, c = i & 7;
        cp16(bbase + r * (STRIDE * 4) + c * 16, Bk + (long)r * K + c * 4);
    }
}

__global__ __launch_bounds__(256, 2)
void gemm_mma(const float* __restrict__ A, const float* __restrict__ Bw,
              const float* __restrict__ bias, const float* __restrict__ Res,
              float* __restrict__ C, int M, int N, int K, int flags)
{
    extern __shared__ char smem[];
    const uint32_t sb = smem_u32(smem);
    // stage layout: A0 A1 B0 B1
    const uint32_t Au[2] = { sb, sb + STAGE_BYTES };
    const uint32_t Bu[2] = { sb + 2 * STAGE_BYTES, sb + 3 * STAGE_BYTES };
    const float* Af[2] = { (const float*)smem,
                           (const float*)(smem + STAGE_BYTES) };
    const float* Bf[2] = { (const float*)(smem + 2 * STAGE_BYTES),
                           (const float*)(smem + 3 * STAGE_BYTES) };

    const int tid = threadIdx.x;
    const int lane = tid & 31;
    const int wid = tid >> 5;
    const int warpM = wid & 3;        // 4 warps along M (32 rows each)
    const int warpN = wid >> 2;       // 2 warps along N (64 cols each)
    const int cm = blockIdx.y * 128;
    const int cn = blockIdx.x * 128;

    float acc[2][8][4];
    #pragma unroll
    for (int mi = 0; mi < 2; ++mi)
        #pragma unroll
        for (int ni = 0; ni < 8; ++ni)
            #pragma unroll
            for (int j = 0; j < 4; ++j) acc[mi][ni][j] = 0.f;

    const int KT = K >> 5;
    load_stage(Au[0], Bu[0], A, Bw, K, cm, cn, 0, tid);
    asm volatile("cp.async.commit_group;" ::: "memory");

    const int la = lane >> 2;   // 0..7
    const int lk = lane & 3;    // 0..3

    for (int kt = 0; kt < KT; ++kt) {
        const int cur = kt & 1;
        if (kt + 1 < KT) {
            load_stage(Au[cur ^ 1], Bu[cur ^ 1], A, Bw, K, cm, cn, kt + 1, tid);
            asm volatile("cp.async.commit_group;" ::: "memory");
            asm volatile("cp.async.wait_group 1;" ::: "memory");
        } else {
            asm volatile("cp.async.wait_group 0;" ::: "memory");
        }
        __syncthreads();

        const uint32_t* As = (const uint32_t*)Af[cur];
        const uint32_t* Bs = (const uint32_t*)Bf[cur];
        #pragma unroll
        for (int ks = 0; ks < 4; ++ks) {
            const int k0 = ks * 8 + lk;
            uint32_t a[2][4];
            #pragma unroll
            for (int mi = 0; mi < 2; ++mi) {
                const int r = warpM * 32 + mi * 16 + la;
                a[mi][0] = As[r * STRIDE + k0];
                a[mi][1] = As[(r + 8) * STRIDE + k0];
                a[mi][2] = As[r * STRIDE + k0 + 4];
                a[mi][3] = As[(r + 8) * STRIDE + k0 + 4];
            }
            #pragma unroll
            for (int ni = 0; ni < 8; ++ni) {
                const int n = warpN * 64 + ni * 8 + la;
                const uint32_t b0 = Bs[n * STRIDE + k0];
                const uint32_t b1 = Bs[n * STRIDE + k0 + 4];
                mma1688(acc[0][ni], a[0], b0, b1);
                mma1688(acc[1][ni], a[1], b0, b1);
            }
        }
        __syncthreads();
    }

    // epilogue from register accumulators
    #pragma unroll
    for (int mi = 0; mi < 2; ++mi) {
        #pragma unroll
        for (int half = 0; half < 2; ++half) {
            const int row = cm + warpM * 32 + mi * 16 + la + half * 8;
            const long rb = (long)row * N;
            #pragma unroll
            for (int ni = 0; ni < 8; ++ni) {
                const int c = cn + warpN * 64 + ni * 8 + lk * 2;
                float v0 = acc[mi][ni][half * 2 + 0] + bias[c];
                float v1 = acc[mi][ni][half * 2 + 1] + bias[c + 1];
                if (flags & FLAG_GELU) {
                    v0 = 0.5f * v0 * (1.0f + erff(v0 * 0.70710678118654752f));
                    v1 = 0.5f * v1 * (1.0f + erff(v1 * 0.70710678118654752f));
                    v0 = rna_f(v0);   // feeds next GEMM's A operand
                    v1 = rna_f(v1);
                }
                if (flags & FLAG_RES) {
                    float2 r = *(const float2*)&Res[rb + c];
                    v0 += r.x; v1 += r.y;
                }
                float2 o; o.x = v0; o.y = v1;
                *(float2*)&C[rb + c] = o;
            }
        }
    }
}

// ---------------------------------------------------------------------------
// Fourier embed + input projection (rna output: feeds kv GEMM)
// ---------------------------------------------------------------------------
__global__ void embed_kernel(const float* __restrict__ pc,
                             const float* __restrict__ feats,
                             const float* __restrict__ inW,
                             const float* __restrict__ inb,
                             float* __restrict__ out)
{
    __shared__ float e[IN_DIM];
    const int row = blockIdx.x;
    const int t = threadIdx.x;
    if (t < IN_DIM) {
        float v;
        if (t < 3) {
            v = pc[row * 3 + t];
        } else if (t < 27) {
            int j = (t - 3) >> 3, f = (t - 3) & 7;
            v = sinf(pc[row * 3 + j] * (float)(1 << f));
        } else if (t < 51) {
            int j = (t - 27) >> 3, f = (t - 27) & 7;
            v = cosf(pc[row * 3 + j] * (float)(1 << f));
        } else {
            v = feats[row * 3 + (t - 51)];
        }
        e[t] = v;
    }
    __syncthreads();
    #pragma unroll
    for (int rep = 0; rep < 3; ++rep) {
        int o = t + rep * 256;
        const float* w = inW + o * IN_DIM;
        float s = inb[o];
        #pragma unroll
        for (int k = 0; k < IN_DIM; ++k) s = fmaf(w[k], e[k], s);
        out[(long)row * WIDTH + o] = rna_f(s);
    }
}

// ---------------------------------------------------------------------------
// LayerNorm (rna output: feeds qkv / fc GEMMs)
// ---------------------------------------------------------------------------
__global__ void ln_kernel(const float* __restrict__ X,
                          const float* __restrict__ s,
                          const float* __restrict__ b,
                          float* __restrict__ Y)
{
    const int row = blockIdx.x;
    const int t = threadIdx.x;
    const float* x = X + (long)row * WIDTH;
    float v0 = x[t], v1 = x[t + 256], v2 = x[t + 512];
    float sum = v0 + v1 + v2;
    float sq = v0 * v0 + v1 * v1 + v2 * v2;
    __shared__ float red[16];
    #pragma unroll
    for (int o = 16; o; o >>= 1) {
        sum += __shfl_xor_sync(0xffffffffu, sum, o);
        sq  += __shfl_xor_sync(0xffffffffu, sq,  o);
    }
    const int w = t >> 5, l = t & 31;
    if (l == 0) { red[w] = sum; red[w + 8] = sq; }
    __syncthreads();
    if (t < 32) {
        float a = (l < 8) ? red[l] : 0.f;
        float c = (l < 8) ? red[l + 8] : 0.f;
        #pragma unroll
        for (int o = 4; o; o >>= 1) {
            a += __shfl_xor_sync(0xffffffffu, a, o);
            c += __shfl_xor_sync(0xffffffffu, c, o);
        }
        if (l == 0) { red[0] = a; red[1] = c; }
    }
    __syncthreads();
    const float mu = red[0] * (1.f / WIDTH);
    const float var = red[1] * (1.f / WIDTH) - mu * mu;
    const float rs = rsqrtf(var + 1e-5f);
    float* y = Y + (long)row * WIDTH;
    y[t]       = rna_f((v0 - mu) * rs * s[t]       + b[t]);
    y[t + 256] = rna_f((v1 - mu) * rs * s[t + 256] + b[t + 256]);
    y[t + 512] = rna_f((v2 - mu) * rs * s[t + 512] + b[t + 512]);
}

// ---------------------------------------------------------------------------
// Flash attention fp32 (rna output: feeds proj GEMM)
// ---------------------------------------------------------------------------
#define FLASH_SMEM ((2 * 128 * 65 + 2 * 64 * 65) * 4)

__global__ __launch_bounds__(256)
void flash_kernel(const float* __restrict__ Qp, const float* __restrict__ Kp,
                  const float* __restrict__ Vp, float* __restrict__ Op,
                  int Lk, int qRS, int kRS, int oRS,
                  long qBS, long kBS, long oBS,
                  int qHS, int kHS, int oHS)
{
    extern __shared__ float sm[];
    float* Qs = sm;
    float* Ps = sm + 128 * 65;
    float* Ks = sm + 2 * 128 * 65;
    float* Vs = Ks + 64 * 65;

    const int tid = threadIdx.x;
    const int tx = tid & 15;
    const int ty = tid >> 4;
    const int qt = blockIdx.x, h = blockIdx.y, b = blockIdx.z;

    const float* Q  = Qp + (long)b * qBS + h * qHS + (long)(qt * 128) * qRS;
    const float* Kb = Kp + (long)b * kBS + h * kHS;
    const float* Vb = Vp + (long)b * kBS + h * kHS;
    float*       O  = Op + (long)b * oBS + h * oHS + (long)(qt * 128) * oRS;

    for (int idx = tid; idx < 128 * 64; idx += 256) {
        int r = idx >> 6, d = idx & 63;
        Qs[r * 65 + d] = Q[(long)r * qRS + d];
    }

    float m[8], l[8], o[8][4];
    #pragma unroll
    for (int i = 0; i < 8; ++i) {
        m[i] = -3.0e38f; l[i] = 0.f;
        #pragma unroll
        for (int j = 0; j < 4; ++j) o[i][j] = 0.f;
    }
    __syncthreads();

    for (int c0 = 0; c0 < Lk; c0 += 64) {
        for (int idx = tid; idx < 64 * 64; idx += 256) {
            int r = idx >> 6, d = idx & 63;
            Ks[r * 65 + d] = Kb[(long)(c0 + r) * kRS + d];
            Vs[r * 65 + d] = Vb[(long)(c0 + r) * kRS + d];
        }
        __syncthreads();

        float s[8][4];
        #pragma unroll
        for (int i = 0; i < 8; ++i)
            #pragma unroll
            for (int j = 0; j < 4; ++j) s[i][j] = 0.f;
        #pragma unroll 16
        for (int d = 0; d < 64; ++d) {
            float a[8], bf[4];
            #pragma unroll
            for (int i = 0; i < 8; ++i) a[i] = Qs[(ty * 8 + i) * 65 + d];
            #pragma unroll
            for (int j = 0; j < 4; ++j) bf[j] = Ks[(tx * 4 + j) * 65 + d];
            #pragma unroll
            for (int i = 0; i < 8; ++i)
                #pragma unroll
                for (int j = 0; j < 4; ++j)
                    s[i][j] = fmaf(a[i], bf[j], s[i][j]);
        }

        #pragma unroll
        for (int i = 0; i < 8; ++i) {
            #pragma unroll
            for (int j = 0; j < 4; ++j) s[i][j] *= 0.125f;
            float mx = fmaxf(fmaxf(s[i][0], s[i][1]), fmaxf(s[i][2], s[i][3]));
            #pragma unroll
            for (int off = 1; off < 16; off <<= 1)
                mx = fmaxf(mx, __shfl_xor_sync(0xffffffffu, mx, off));
            const float mnew = fmaxf(m[i], mx);
            const float corr = __expf(m[i] - mnew);
            m[i] = mnew;
            float rsum = 0.f;
            #pragma unroll
            for (int j = 0; j < 4; ++j) {
                s[i][j] = __expf(s[i][j] - mnew);
                rsum += s[i][j];
            }
            #pragma unroll
            for (int off = 1; off < 16; off <<= 1)
                rsum += __shfl_xor_sync(0xffffffffu, rsum, off);
            l[i] = l[i] * corr + rsum;
            #pragma unroll
            for (int j = 0; j < 4; ++j) {
                o[i][j] *= corr;
                Ps[(ty * 8 + i) * 65 + tx * 4 + j] = s[i][j];
            }
        }
        __syncthreads();

        #pragma unroll 16
        for (int c = 0; c < 64; ++c) {
            float a[8], bf[4];
            #pragma unroll
            for (int i = 0; i < 8; ++i) a[i] = Ps[(ty * 8 + i) * 65 + c];
            #pragma unroll
            for (int j = 0; j < 4; ++j) bf[j] = Vs[c * 65 + tx * 4 + j];
            #pragma unroll
            for (int i = 0; i < 8; ++i)
                #pragma unroll
                for (int j = 0; j < 4; ++j)
                    o[i][j] = fmaf(a[i], bf[j], o[i][j]);
        }
        __syncthreads();
    }

    #pragma unroll
    for (int i = 0; i < 8; ++i) {
        const float inv = 1.f / l[i];
        const int r = ty * 8 + i;
        #pragma unroll
        for (int j = 0; j < 4; ++j)
            O[(long)r * oRS + tx * 4 + j] = rna_f(o[i][j] * inv);
    }
}

__global__ void copy_kernel(const float* __restrict__ src, float* __restrict__ dst, int n)
{
    int i = blockIdx.x * 256 + threadIdx.x;
    if (i < n) dst[i] = src[i];
}

// ---------------------------------------------------------------------------
// kernel_launch
// ---------------------------------------------------------------------------
static inline void rna(const float* src, float* dst, long n)
{
    int n4 = (int)(n >> 2);
    rna_kernel<<<(n4 + 255) / 256, 256>>>((const float4*)src, (float4*)dst, n4);
}

extern "C" void kernel_launch(void* const* d_in, const int* in_sizes, int n_in,
                              void* d_out, int out_size)
{
    const float* pc       = (const float*)d_in[0];
    const float* feats    = (const float*)d_in[1];
    const float* query    = (const float*)d_in[2];
    const float* in_W     = (const float*)d_in[3];
    const float* in_b     = (const float*)d_in[4];
    const float* ca_qkv_W = (const float*)d_in[5];
    const float* ca_qkv_b = (const float*)d_in[6];
    const float* ca_proj_W= (const float*)d_in[7];
    const float* ca_proj_b= (const float*)d_in[8];
    const float* ln1_s    = (const float*)d_in[9];
    const float* ln1_b    = (const float*)d_in[10];
    const float* qkv_W    = (const float*)d_in[11];
    const float* qkv_b    = (const float*)d_in[12];
    const float* proj_W   = (const float*)d_in[13];
    const float* proj_b   = (const float*)d_in[14];
    const float* ln2_s    = (const float*)d_in[15];
    const float* ln2_b    = (const float*)d_in[16];
    const float* fc_W     = (const float*)d_in[17];
    const float* fc_b     = (const float*)d_in[18];
    const float* fc2_W    = (const float*)d_in[19];
    const float* fc2_b    = (const float*)d_in[20];

    float *data, *kv, *qb, *attn, *x, *h, *ffn, *wtf;
    cudaGetSymbolAddress((void**)&data, g_data);
    cudaGetSymbolAddress((void**)&kv,   g_kv);
    cudaGetSymbolAddress((void**)&qb,   g_q);
    cudaGetSymbolAddress((void**)&attn, g_attn);
    cudaGetSymbolAddress((void**)&x,    g_x);
    cudaGetSymbolAddress((void**)&h,    g_h);
    cudaGetSymbolAddress((void**)&ffn,  g_ffn);
    cudaGetSymbolAddress((void**)&wtf,  g_wtf);

    cudaFuncSetAttribute(flash_kernel, cudaFuncAttributeMaxDynamicSharedMemorySize,
                         FLASH_SMEM);
    cudaFuncSetAttribute(gemm_mma, cudaFuncAttributeMaxDynamicSharedMemorySize,
                         GEMM_SMEM);

    // 0) round all weights to tf32 (rna)
    rna(ca_qkv_W,  wtf + W_CAQKV,  2304L * 768);
    rna(ca_proj_W, wtf + W_CAPROJ, 768L * 768);
    rna(qkv_W,     wtf + W_QKV,    (long)LAYERS * 2304 * 768);
    rna(proj_W,    wtf + W_PROJ,   (long)LAYERS * 768 * 768);
    rna(fc_W,      wtf + W_FC,     (long)LAYERS * 3072 * 768);
    rna(fc2_W,     wtf + W_FC2,    (long)LAYERS * 768 * 3072);

    // 1) fourier embed + input projection
    embed_kernel<<<BN_ROWS, 256>>>(pc, feats, in_W, in_b, data);

    // 2) kv = data @ ca_qkv_W[768:2304].T + b[768:]
    gemm_mma<<<dim3((2 * WIDTH) / 128, BN_ROWS / 128), 256, GEMM_SMEM>>>(
        data, wtf + W_CAQKV + (long)WIDTH * WIDTH, ca_qkv_b + WIDTH, nullptr, kv,
        BN_ROWS, 2 * WIDTH, WIDTH, 0);

    // 3) q = query @ ca_qkv_W[:768].T + b[:768]
    gemm_mma<<<dim3(WIDTH / 128, N_LAT / 128), 256, GEMM_SMEM>>>(
        query, wtf + W_CAQKV, ca_qkv_b, nullptr, qb, N_LAT, WIDTH, WIDTH, 0);

    // 4) cross attention
    flash_kernel<<<dim3(N_LAT / 128, HEADS, BATCH), 256, FLASH_SMEM>>>(
        qb, kv, kv + WIDTH, attn,
        NPTS, WIDTH, 2 * WIDTH, WIDTH,
        0L, (long)NPTS * 2 * WIDTH, (long)N_LAT * WIDTH,
        D_HEAD, D_HEAD, D_HEAD);

    // 5) latents = attn @ ca_proj_W.T + b
    gemm_mma<<<dim3(WIDTH / 128, LAT_ROWS / 128), 256, GEMM_SMEM>>>(
        attn, wtf + W_CAPROJ, ca_proj_b, nullptr, x, LAT_ROWS, WIDTH, WIDTH, 0);

    // 6) transformer blocks
    for (int L = 0; L < LAYERS; ++L) {
        ln_kernel<<<LAT_ROWS, 256>>>(x, ln1_s + L * WIDTH, ln1_b + L * WIDTH, h);

        float* qkvb = ffn;  // reuse 4*WIDTH scratch for 3*WIDTH qkv
        gemm_mma<<<dim3((3 * WIDTH) / 128, LAT_ROWS / 128), 256, GEMM_SMEM>>>(
            h, wtf + W_QKV + (long)L * 3 * WIDTH * WIDTH, qkv_b + (long)L * 3 * WIDTH,
            nullptr, qkvb, LAT_ROWS, 3 * WIDTH, WIDTH, 0);

        flash_kernel<<<dim3(N_LAT / 128, HEADS, BATCH), 256, FLASH_SMEM>>>(
            qkvb, qkvb + D_HEAD, qkvb + 2 * D_HEAD, attn,
            N_LAT, 3 * WIDTH, 3 * WIDTH, WIDTH,
            (long)N_LAT * 3 * WIDTH, (long)N_LAT * 3 * WIDTH, (long)N_LAT * WIDTH,
            3 * D_HEAD, 3 * D_HEAD, D_HEAD);

        gemm_mma<<<dim3(WIDTH / 128, LAT_ROWS / 128), 256, GEMM_SMEM>>>(
            attn, wtf + W_PROJ + (long)L * WIDTH * WIDTH, proj_b + (long)L * WIDTH,
            x, x, LAT_ROWS, WIDTH, WIDTH, FLAG_RES);

        ln_kernel<<<LAT_ROWS, 256>>>(x, ln2_s + L * WIDTH, ln2_b + L * WIDTH, h);

        gemm_mma<<<dim3((4 * WIDTH) / 128, LAT_ROWS / 128), 256, GEMM_SMEM>>>(
            h, wtf + W_FC + (long)L * 4 * WIDTH * WIDTH, fc_b + (long)L * 4 * WIDTH,
            nullptr, ffn, LAT_ROWS, 4 * WIDTH, WIDTH, FLAG_GELU);

        float* Cout = (L == LAYERS - 1) ? (float*)d_out : x;
        gemm_mma<<<dim3(WIDTH / 128, LAT_ROWS / 128), 256, GEMM_SMEM>>>(
            ffn, wtf + W_FC2 + (long)L * WIDTH * 4 * WIDTH, fc2_b + (long)L * WIDTH,
            x, Cout, LAT_ROWS, WIDTH, 4 * WIDTH, FLAG_RES);
    }

    // 7) pc passthrough if output holds both
    const int lat_elems = LAT_ROWS * WIDTH;
    const int pc_elems = BATCH * NPTS * 3;
    if (out_size >= lat_elems + pc_elems) {
        copy_kernel<<<(pc_elems + 255) / 256, 256>>>(
            pc, (float*)d_out + lat_elems, pc_elems);
    }
}